// round 15
// baseline (speedup 1.0000x reference)
#include <cuda_runtime.h>
#include <math.h>
#include <stdint.h>

// Problem constants: B=32, T=1024, D=256, H=256
#define BB 32
#define TT 1024
#define DD 256
#define HH 256
#define GRID 148
#define NTHREADS 1024
#define TILE_ROWS 32
#define TILE_BYTES (TILE_ROWS * DD * 4)      // 32768
#define NTILES 1024
#define NBUF 7                                // resident tiles per CTA (max slab)
#define DYN_SMEM (NBUF * TILE_BYTES)          // 229376 <= 232448 (227 KB limit)

// Scratch (device globals — no allocation allowed)
__device__ __align__(16) float g_partial[GRID * 2 * 16 * DD];  // [cta][seg][r2][d]  9.7 MB
__device__ __align__(16) float g_W[BB * DD];
__device__ __align__(16) float g_bias[BB * DD];
__device__ unsigned g_ticket = 0;            // barrier tickets (monotonic)
__device__ volatile unsigned g_gen = 0;      // barrier generation (monotonic)

// ---------------------------------------------------------------------------
// PTX helpers
// ---------------------------------------------------------------------------
__device__ __forceinline__ unsigned smem_u32(const void* p) {
    return (unsigned)__cvta_generic_to_shared(p);
}
__device__ __forceinline__ void mbar_init(unsigned a, unsigned cnt) {
    asm volatile("mbarrier.init.shared.b64 [%0], %1;" :: "r"(a), "r"(cnt) : "memory");
}
__device__ __forceinline__ void mbar_expect_tx(unsigned a, unsigned bytes) {
    asm volatile("mbarrier.arrive.expect_tx.shared.b64 _, [%0], %1;"
                 :: "r"(a), "r"(bytes) : "memory");
}
__device__ __forceinline__ void mbar_wait(unsigned a, int phase) {
    asm volatile(
        "{\n\t.reg .pred P;\n\t"
        "W_%=:\n\t"
        "mbarrier.try_wait.parity.acquire.cta.shared::cta.b64 P, [%0], %1, 0x989680;\n\t"
        "@P bra D_%=;\n\t"
        "bra W_%=;\n\t"
        "D_%=:\n\t}"
        :: "r"(a), "r"((unsigned)phase) : "memory");
}
__device__ __forceinline__ void bulk_load(unsigned dst_smem, const void* src_gmem,
                                          unsigned bytes, unsigned mbar) {
    asm volatile(
        "cp.async.bulk.shared::cluster.global.mbarrier::complete_tx::bytes "
        "[%0], [%1], %2, [%3];"
        :: "r"(dst_smem), "l"(src_gmem), "r"(bytes), "r"(mbar) : "memory");
}
__device__ __forceinline__ void bulk_store(void* dst_gmem, unsigned src_smem,
                                           unsigned bytes) {
    asm volatile("cp.async.bulk.global.shared::cta.bulk_group [%0], [%1], %2;"
                 :: "l"(dst_gmem), "r"(src_smem), "r"(bytes) : "memory");
}
__device__ __forceinline__ void bulk_commit()      { asm volatile("cp.async.bulk.commit_group;" ::: "memory"); }
__device__ __forceinline__ void bulk_wait_group0() { asm volatile("cp.async.bulk.wait_group 0;" ::: "memory"); }
__device__ __forceinline__ void fence_proxy_async_shared() {
    asm volatile("fence.proxy.async.shared::cta;" ::: "memory");
}

// ---------------------------------------------------------------------------
// Grid barrier (proven R7/R10): 148 arrivals, plain-load spin, never resets.
// Exactly 2 barriers per launch.
// ---------------------------------------------------------------------------
__device__ __forceinline__ void grid_barrier() {
    __syncthreads();
    if (threadIdx.x == 0) {
        __threadfence();
        unsigned gv = g_gen;
        unsigned t = atomicAdd(&g_ticket, 1u);
        if ((t % GRID) == GRID - 1u) {
            __threadfence();
            g_gen = gv + 1u;
        } else {
            while (g_gen == gv) { __nanosleep(32); }
        }
        __threadfence();
    }
    __syncthreads();
}

__device__ __forceinline__ float gelu_exact(float v) {
    return 0.5f * v * (1.0f + erff(v * 0.70710678118654752f));
}
__device__ __forceinline__ float dot4(float4 a, float4 b) {
    return fmaf(a.x, b.x, fmaf(a.y, b.y, fmaf(a.z, b.z, a.w * b.w)));
}
__device__ __forceinline__ int slab_lo(int c) { return (int)(((long)c * NTILES) / GRID); }

extern __shared__ __align__(128) char dynsmem[];

// ---------------------------------------------------------------------------
// Persistent kernel: x fully resident in smem. Load once, reduce, MLP, apply
// in place, store once. x is read from DRAM exactly once.
// ---------------------------------------------------------------------------
__global__ __launch_bounds__(NTHREADS, 1) void fused_kernel(
        const float* __restrict__ x,
        const int* __restrict__ len,
        const float* __restrict__ w1w, const float* __restrict__ w1b,
        const float* __restrict__ w2w, const float* __restrict__ w2b,
        const float* __restrict__ q1w, const float* __restrict__ q1b,
        const float* __restrict__ q2w, const float* __restrict__ q2b,
        float* __restrict__ out) {
    __shared__ __align__(16) float c_sh[DD];
    __shared__ __align__(16) float h_sh[HH];
    __shared__ __align__(8) unsigned long long mbar_s[NBUF];

    const int tid = threadIdx.x;
    const int d4  = tid & 63;
    const int r2  = tid >> 6;        // rows r2 and r2+16 of a tile
    const char* xb = (const char*)x;
    char*       ob = (char*)out;
    float4*   out4 = (float4*)out;

    // Balanced global slab: 6 or 7 tiles, spans <= 2 batches. ALL resident.
    const int t0 = slab_lo(blockIdx.x);
    const int t1 = slab_lo(blockIdx.x + 1);
    const int nt = t1 - t0;
    const int b0 = t0 >> 5;
    const int b1 = (t1 - 1) >> 5;
    const int tb = (b0 + 1) * 32;    // first tile of next batch
    const bool is_mlp = (blockIdx.x < 2 * BB);

    unsigned mb[NBUF], bufa[NBUF];
#pragma unroll
    for (int k = 0; k < NBUF; k++) {
        mb[k]   = smem_u32(&mbar_s[k]);
        bufa[k] = smem_u32(dynsmem) + k * TILE_BYTES;
    }
    if (tid == 0) {
#pragma unroll
        for (int k = 0; k < NBUF; k++) mbar_init(mb[k], 1);
    }
    __syncthreads();
    float4* const bufs = (float4*)dynsmem;

    // ---------- Phase 1: load ENTIRE slab (<=224 KB in flight), reduce ----------
    {
        if (tid == 0) {
            for (int j = 0; j < nt; j++) {
                mbar_expect_tx(mb[j], TILE_BYTES);
                bulk_load(bufa[j], xb + (size_t)(t0 + j) * TILE_BYTES, TILE_BYTES, mb[j]);
            }
        }
        float4 accA = make_float4(0.f, 0.f, 0.f, 0.f);
        float4 accB = make_float4(0.f, 0.f, 0.f, 0.f);
        for (int i = 0; i < nt; i++) {
            mbar_wait(mb[i], 0);                 // each mbar used exactly once
            float4 v0 = bufs[i * 2048 + r2 * 64 + d4];
            float4 v1 = bufs[i * 2048 + (r2 + 16) * 64 + d4];
            float4 v = make_float4(v0.x + v1.x, v0.y + v1.y, v0.z + v1.z, v0.w + v1.w);
            if (t0 + i < tb) { accA.x += v.x; accA.y += v.y; accA.z += v.z; accA.w += v.w; }
            else             { accB.x += v.x; accB.y += v.y; accB.z += v.z; accB.w += v.w; }
        }
        // flush per-thread partials straight to gmem — no staging, no syncs
        float4* gp4 = reinterpret_cast<float4*>(g_partial);
        gp4[((blockIdx.x * 2 + 0) * 16 + r2) * 64 + d4] = accA;
        if (b1 > b0)
            gp4[((blockIdx.x * 2 + 1) * 16 + r2) * 64 + d4] = accB;
    }
    grid_barrier();   // #1: all partials visible

    // ---------- Phase 2: MLP (CTAs 0..63) || early zero-store invalid tiles ----------
    if (is_mlp) {
        int bm = blockIdx.x >> 1;
        int branch = blockIdx.x & 1;
        const float* m1w = branch ? q1w : w1w;
        const float* m1b = branch ? q1b : w1b;
        const float* m2w = branch ? q2w : w2w;
        const float* m2b = branch ? q2b : w2b;
        float* gout = branch ? g_bias : g_W;

        // gather c: scan contributing (cta, seg) partials, 16 rows each
        if (tid < DD) {
            float s = 0.0f;
            for (int c = 0; c < GRID; c++) {
                int ct0 = slab_lo(c), ct1 = slab_lo(c + 1);
                int cb0 = ct0 >> 5, cb1 = (ct1 - 1) >> 5;
                int seg = -1;
                if (cb0 == bm) seg = 0;
                else if (cb1 == bm) seg = 1;
                if (seg >= 0) {
                    const float* p = g_partial + ((c * 2 + seg) * 16) * DD + tid;
#pragma unroll
                    for (int r = 0; r < 16; r++) s += p[r * DD];
                }
            }
            c_sh[tid] = s / (float)len[bm];
        }
        __syncthreads();

        int w = tid >> 5, lane = tid & 31;     // 32 warps x 8 outputs (R10 MLP)
        const float4* c4 = reinterpret_cast<const float4*>(c_sh);
        const float4* h4 = reinterpret_cast<const float4*>(h_sh);
#pragma unroll
        for (int jj = 0; jj < 8; jj++) {
            int o = w * 8 + jj;
            const float4* row = reinterpret_cast<const float4*>(m1w + (size_t)o * DD);
            float acc = dot4(c4[lane], row[lane]) + dot4(c4[lane + 32], row[lane + 32]);
#pragma unroll
            for (int off = 16; off > 0; off >>= 1)
                acc += __shfl_down_sync(0xFFFFFFFFu, acc, off);
            if (lane == 0) h_sh[o] = gelu_exact(acc + m1b[o]);
        }
        __syncthreads();
#pragma unroll
        for (int jj = 0; jj < 8; jj++) {
            int o = w * 8 + jj;
            const float4* row = reinterpret_cast<const float4*>(m2w + (size_t)o * HH);
            float acc = dot4(h4[lane], row[lane]) + dot4(h4[lane + 32], row[lane + 32]);
#pragma unroll
            for (int off = 16; off > 0; off >>= 1)
                acc += __shfl_down_sync(0xFFFFFFFFu, acc, off);
            if (lane == 0) gout[bm * DD + o] = acc + m2b[o];
        }
    } else {
        // idle CTAs: zero-store fully-invalid tiles now (direct STG; smem untouched)
        const float4 zero = make_float4(0.f, 0.f, 0.f, 0.f);
        for (int i = 0; i < nt; i++) {
            int gt = t0 + i;
            int bcur = gt >> 5;
            int L = __ldg(&len[bcur]);
            if ((gt & 31) * TILE_ROWS >= L) {
                size_t base = (size_t)gt * 2048;
                __stcs(&out4[base + r2 * 64 + d4], zero);
                __stcs(&out4[base + (r2 + 16) * 64 + d4], zero);
            }
        }
    }
    grid_barrier();   // #2: g_W / g_bias complete

    // ---------- Phase 3: apply IN PLACE on resident tiles, bulk_store each ----------
    {
        const float4* gW4 = reinterpret_cast<const float4*>(g_W);
        const float4* gB4 = reinterpret_cast<const float4*>(g_bias);
        const float4 zero = make_float4(0.f, 0.f, 0.f, 0.f);

        for (int i = 0; i < nt; i++) {
            int gt = t0 + i;
            int bcur = gt >> 5;
            int L = __ldg(&len[bcur]);
            int tbase = (gt & 31) * TILE_ROWS;
            size_t gbase = (size_t)gt * 2048;

            if (tbase < L) {
                float4 wv = gW4[bcur * 64 + d4];
                // row r2
                {
                    int t = tbase + r2;
                    float4 o = zero;
                    if (t < L) {
                        float4 xv = bufs[i * 2048 + r2 * 64 + d4];
                        o.x = fmaf(xv.x, wv.x, xv.x);
                        o.y = fmaf(xv.y, wv.y, xv.y);
                        o.z = fmaf(xv.z, wv.z, xv.z);
                        o.w = fmaf(xv.w, wv.w, xv.w);
                        if (t == 0) {
                            float4 bv = gB4[bcur * 64 + d4];
                            o.x += bv.x; o.y += bv.y; o.z += bv.z; o.w += bv.w;
                        }
                    }
                    bufs[i * 2048 + r2 * 64 + d4] = o;
                }
                // row r2+16
                {
                    int t = tbase + r2 + 16;
                    float4 o = zero;
                    if (t < L) {
                        float4 xv = bufs[i * 2048 + (r2 + 16) * 64 + d4];
                        o.x = fmaf(xv.x, wv.x, xv.x);
                        o.y = fmaf(xv.y, wv.y, xv.y);
                        o.z = fmaf(xv.z, wv.z, xv.z);
                        o.w = fmaf(xv.w, wv.w, xv.w);
                    }
                    bufs[i * 2048 + (r2 + 16) * 64 + d4] = o;
                }
                __syncthreads();                  // tile fully rewritten
                if (tid == 0) {
                    fence_proxy_async_shared();
                    bulk_store(ob + (size_t)gt * TILE_BYTES, bufa[i], TILE_BYTES);
                    bulk_commit();                // fire-and-forget; drain at end
                }
            } else if (is_mlp) {
                // MLP CTAs store their invalid tiles' zeros here
                __stcs(&out4[gbase + r2 * 64 + d4], zero);
                __stcs(&out4[gbase + (r2 + 16) * 64 + d4], zero);
            }
        }
        if (tid == 0) bulk_wait_group0();         // drain all stores before exit
        __syncthreads();
    }
}

// ---------------------------------------------------------------------------
extern "C" void kernel_launch(void* const* d_in, const int* in_sizes, int n_in,
                              void* d_out, int out_size) {
    const float* x     = (const float*)d_in[0];
    const int*   len_x = (const int*)d_in[1];
    const float* Ww1_w = (const float*)d_in[2];
    const float* Ww1_b = (const float*)d_in[3];
    const float* Ww2_w = (const float*)d_in[4];
    const float* Ww2_b = (const float*)d_in[5];
    const float* Wb1_w = (const float*)d_in[6];
    const float* Wb1_b = (const float*)d_in[7];
    const float* Wb2_w = (const float*)d_in[8];
    const float* Wb2_b = (const float*)d_in[9];
    float* out = (float*)d_out;

    cudaFuncSetAttribute(fused_kernel,
                         cudaFuncAttributeMaxDynamicSharedMemorySize, DYN_SMEM);
    fused_kernel<<<GRID, NTHREADS, DYN_SMEM>>>(
        x, len_x,
        Ww1_w, Ww1_b, Ww2_w, Ww2_b,
        Wb1_w, Wb1_b, Wb2_w, Wb2_b,
        out);
}

// round 16
// speedup vs baseline: 1.2206x; 1.2206x over previous
#include <cuda_runtime.h>
#include <math.h>
#include <stdint.h>

// Problem constants: B=32, T=1024, D=256, H=256
#define BB 32
#define TT 1024
#define DD 256
#define HH 256
#define GRID 148
#define NTHREADS 1024
#define TILE_ROWS 32
#define TILE_BYTES (TILE_ROWS * DD * 4)      // 32768
#define TILES_PER_BATCH (TT / TILE_ROWS)     // 32
#define NBUF 6                                // load ring (all 6 slots, both phases)
#define DYN_SMEM (NBUF * TILE_BYTES)          // 196608

// Scratch (device globals — no allocation allowed)
__device__ __align__(16) float g_partial[GRID * DD];   // one partial per CTA
__device__ __align__(16) float g_W[BB * DD];
__device__ __align__(16) float g_bias[BB * DD];
__device__ unsigned g_ticket = 0;            // barrier tickets (monotonic)
__device__ volatile unsigned g_gen = 0;      // barrier generation (monotonic)

// ---------------------------------------------------------------------------
// PTX helpers
// ---------------------------------------------------------------------------
__device__ __forceinline__ unsigned smem_u32(const void* p) {
    return (unsigned)__cvta_generic_to_shared(p);
}
__device__ __forceinline__ void mbar_init(unsigned a, unsigned cnt) {
    asm volatile("mbarrier.init.shared.b64 [%0], %1;" :: "r"(a), "r"(cnt) : "memory");
}
__device__ __forceinline__ void mbar_expect_tx(unsigned a, unsigned bytes) {
    asm volatile("mbarrier.arrive.expect_tx.shared.b64 _, [%0], %1;"
                 :: "r"(a), "r"(bytes) : "memory");
}
__device__ __forceinline__ void mbar_wait(unsigned a, int phase) {
    asm volatile(
        "{\n\t.reg .pred P;\n\t"
        "W_%=:\n\t"
        "mbarrier.try_wait.parity.acquire.cta.shared::cta.b64 P, [%0], %1, 0x989680;\n\t"
        "@P bra D_%=;\n\t"
        "bra W_%=;\n\t"
        "D_%=:\n\t}"
        :: "r"(a), "r"((unsigned)phase) : "memory");
}
__device__ __forceinline__ void bulk_load(unsigned dst_smem, const void* src_gmem,
                                          unsigned bytes, unsigned mbar) {
    asm volatile(
        "cp.async.bulk.shared::cluster.global.mbarrier::complete_tx::bytes "
        "[%0], [%1], %2, [%3];"
        :: "r"(dst_smem), "l"(src_gmem), "r"(bytes), "r"(mbar) : "memory");
}
__device__ __forceinline__ void bulk_store(void* dst_gmem, unsigned src_smem,
                                           unsigned bytes) {
    asm volatile("cp.async.bulk.global.shared::cta.bulk_group [%0], [%1], %2;"
                 :: "l"(dst_gmem), "r"(src_smem), "r"(bytes) : "memory");
}
__device__ __forceinline__ void bulk_commit()      { asm volatile("cp.async.bulk.commit_group;" ::: "memory"); }
__device__ __forceinline__ void bulk_wait_group2() { asm volatile("cp.async.bulk.wait_group 2;" ::: "memory"); }
__device__ __forceinline__ void bulk_wait_group0() { asm volatile("cp.async.bulk.wait_group 0;" ::: "memory"); }
__device__ __forceinline__ void fence_proxy_async_shared() {
    asm volatile("fence.proxy.async.shared::cta;" ::: "memory");
}

// ---------------------------------------------------------------------------
// Grid barrier (proven R7/R10): 148 arrivals, plain-load spin, never resets.
// Exactly 2 barriers per launch.
// ---------------------------------------------------------------------------
__device__ __forceinline__ void grid_barrier() {
    __syncthreads();
    if (threadIdx.x == 0) {
        __threadfence();
        unsigned gv = g_gen;
        unsigned t = atomicAdd(&g_ticket, 1u);
        if ((t % GRID) == GRID - 1u) {
            __threadfence();
            g_gen = gv + 1u;
        } else {
            while (g_gen == gv) { __nanosleep(32); }
        }
        __threadfence();
    }
    __syncthreads();
}

__device__ __forceinline__ float gelu_exact(float v) {
    return 0.5f * v * (1.0f + erff(v * 0.70710678118654752f));
}
__device__ __forceinline__ float dot4(float4 a, float4 b) {
    return fmaf(a.x, b.x, fmaf(a.y, b.y, fmaf(a.z, b.z, a.w * b.w)));
}

extern __shared__ __align__(128) char dynsmem[];

// ---------------------------------------------------------------------------
// Persistent kernel (R10 base): TMA reduce -> MLP -> in-place TMA apply
// ---------------------------------------------------------------------------
__global__ __launch_bounds__(NTHREADS, 1) void fused_kernel(
        const float* __restrict__ x,
        const int* __restrict__ len,
        const float* __restrict__ w1w, const float* __restrict__ w1b,
        const float* __restrict__ w2w, const float* __restrict__ w2b,
        const float* __restrict__ q1w, const float* __restrict__ q1b,
        const float* __restrict__ q2w, const float* __restrict__ q2b,
        float* __restrict__ out) {
    __shared__ __align__(16) float c_sh[DD];
    __shared__ __align__(16) float h_sh[HH];
    __shared__ __align__(8) unsigned long long mbar_s[NBUF];

    const int tid = threadIdx.x;
    const int d4  = tid & 63;
    const int r2  = tid >> 6;        // rows r2 and r2+16 of a tile
    const char* xb = (const char*)x;
    char*       ob = (char*)out;

    // Per-batch slab (R10): CTA -> one batch, contiguous tiles (6-8).
    const int b   = (blockIdx.x * BB) / GRID;
    const int lo  = (b * GRID + BB - 1) / BB;
    const int hi  = ((b + 1) * GRID + BB - 1) / BB;
    const int idx = blockIdx.x - lo;
    const int n   = hi - lo;
    const int t0  = b * TILES_PER_BATCH + (idx * TILES_PER_BATCH) / n;
    const int t1  = b * TILES_PER_BATCH + ((idx + 1) * TILES_PER_BATCH) / n;
    const int nt  = t1 - t0;

    unsigned mb[NBUF], bufa[NBUF];
#pragma unroll
    for (int k = 0; k < NBUF; k++) {
        mb[k]   = smem_u32(&mbar_s[k]);
        bufa[k] = smem_u32(dynsmem) + k * TILE_BYTES;
    }
    if (tid == 0) {
#pragma unroll
        for (int k = 0; k < NBUF; k++) mbar_init(mb[k], 1);
    }
    __syncthreads();
    int ph[NBUF] = {0, 0, 0, 0, 0, 0};
    float4* const bufs = (float4*)dynsmem;

    // ---------- Phase 1: reduce via NBUF-deep TMA ring ----------
    // Each smem location is read by exactly ONE thread, so no per-iteration
    // __syncthreads is needed except right before a slot is reissued.
    {
        if (tid == 0) {
            int pre = nt < NBUF ? nt : NBUF;
            for (int j = 0; j < pre; j++) {
                mbar_expect_tx(mb[j], TILE_BYTES);
                bulk_load(bufa[j], xb + (size_t)(t0 + j) * TILE_BYTES, TILE_BYTES, mb[j]);
            }
        }
        float4 acc0 = make_float4(0.f, 0.f, 0.f, 0.f);
        float4 acc1 = make_float4(0.f, 0.f, 0.f, 0.f);
        for (int i = 0; i < nt; i++) {
            int s = i % NBUF;
            mbar_wait(mb[s], ph[s]); ph[s] ^= 1;
            float4 v0 = bufs[s * 2048 + r2 * 64 + d4];
            float4 v1 = bufs[s * 2048 + (r2 + 16) * 64 + d4];
            acc0.x += v0.x; acc0.y += v0.y; acc0.z += v0.z; acc0.w += v0.w;
            acc1.x += v1.x; acc1.y += v1.y; acc1.z += v1.z; acc1.w += v1.w;
            if (i + NBUF < nt) {                 // reissue (<=2 per launch)
                __syncthreads();                 // all threads done with slot s
                if (tid == 0) {
                    mbar_expect_tx(mb[s], TILE_BYTES);
                    bulk_load(bufa[s], xb + (size_t)(t0 + i + NBUF) * TILE_BYTES, TILE_BYTES, mb[s]);
                }
            }
        }
        // flush: stage own address in slot-0 region (single-writer == single-
        // reader address -> race-free without a sync), then 16->1 reduce.
        acc0.x += acc1.x; acc0.y += acc1.y; acc0.z += acc1.z; acc0.w += acc1.w;
        bufs[r2 * 64 + d4] = acc0;
        __syncthreads();
        if (tid < 64) {
            float4 a = make_float4(0.f, 0.f, 0.f, 0.f);
#pragma unroll
            for (int r = 0; r < 16; r++) {
                float4 v = bufs[r * 64 + tid];
                a.x += v.x; a.y += v.y; a.z += v.z; a.w += v.w;
            }
            reinterpret_cast<float4*>(g_partial)[blockIdx.x * 64 + tid] = a;
        }
        __syncthreads();
        // phase-3 prefetch: all NBUF slots (deeper than R10's 4)
        if (tid == 0) {
            int pre = nt < NBUF ? nt : NBUF;
            for (int j = 0; j < pre; j++) {
                mbar_expect_tx(mb[j], TILE_BYTES);
                bulk_load(bufa[j], xb + (size_t)(t0 + j) * TILE_BYTES, TILE_BYTES, mb[j]);
            }
        }
    }
    grid_barrier();   // #1: all partials visible

    // ---------- Phase 2: MLPs on CTAs 0..63 (R10 verbatim) ----------
    if (blockIdx.x < 2 * BB) {
        int bm = blockIdx.x >> 1;
        int branch = blockIdx.x & 1;
        const float* m1w = branch ? q1w : w1w;
        const float* m1b = branch ? q1b : w1b;
        const float* m2w = branch ? q2w : w2w;
        const float* m2b = branch ? q2b : w2b;
        float* gout = branch ? g_bias : g_W;

        if (tid < DD) {
            int lo2 = (bm * GRID + BB - 1) / BB;
            int hi2 = ((bm + 1) * GRID + BB - 1) / BB;
            float s = 0.0f;
            for (int c = lo2; c < hi2; c++) s += g_partial[c * DD + tid];
            c_sh[tid] = s / (float)len[bm];
        }
        __syncthreads();

        int w = tid >> 5, lane = tid & 31;     // 32 warps x 8 outputs
        const float4* c4 = reinterpret_cast<const float4*>(c_sh);
        const float4* h4 = reinterpret_cast<const float4*>(h_sh);
#pragma unroll
        for (int jj = 0; jj < 8; jj++) {
            int o = w * 8 + jj;
            const float4* row = reinterpret_cast<const float4*>(m1w + (size_t)o * DD);
            float acc = dot4(c4[lane], row[lane]) + dot4(c4[lane + 32], row[lane + 32]);
#pragma unroll
            for (int off = 16; off > 0; off >>= 1)
                acc += __shfl_down_sync(0xFFFFFFFFu, acc, off);
            if (lane == 0) h_sh[o] = gelu_exact(acc + m1b[o]);
        }
        __syncthreads();
#pragma unroll
        for (int jj = 0; jj < 8; jj++) {
            int o = w * 8 + jj;
            const float4* row = reinterpret_cast<const float4*>(m2w + (size_t)o * HH);
            float acc = dot4(h4[lane], row[lane]) + dot4(h4[lane + 32], row[lane + 32]);
#pragma unroll
            for (int off = 16; off > 0; off >>= 1)
                acc += __shfl_down_sync(0xFFFFFFFFu, acc, off);
            if (lane == 0) gout[bm * DD + o] = acc + m2b[o];
        }
    }
    grid_barrier();   // #2: g_W / g_bias complete

    // ---------- Phase 3: in-place apply, store straight from the load slot ----------
    {
        const int L = __ldg(&len[b]);
        float4 wv = reinterpret_cast<const float4*>(g_W)[b * 64 + d4];
        float4 bv = reinterpret_cast<const float4*>(g_bias)[b * 64 + d4];
        const float4 zero = make_float4(0.f, 0.f, 0.f, 0.f);

        for (int j = 0; j < nt; j++) {
            int s = j % NBUF;
            mbar_wait(mb[s], ph[s]); ph[s] ^= 1;

            int tbase = (t0 + j) * TILE_ROWS - b * TT;
            // row r2 (in place: each thread rewrites only what it read)
            {
                int t = tbase + r2;
                float4 o = zero;
                if (t < L) {
                    float4 xv = bufs[s * 2048 + r2 * 64 + d4];
                    o.x = fmaf(xv.x, wv.x, xv.x);
                    o.y = fmaf(xv.y, wv.y, xv.y);
                    o.z = fmaf(xv.z, wv.z, xv.z);
                    o.w = fmaf(xv.w, wv.w, xv.w);
                    if (t == 0) { o.x += bv.x; o.y += bv.y; o.z += bv.z; o.w += bv.w; }
                }
                bufs[s * 2048 + r2 * 64 + d4] = o;
            }
            // row r2+16
            {
                int t = tbase + r2 + 16;
                float4 o = zero;
                if (t < L) {
                    float4 xv = bufs[s * 2048 + (r2 + 16) * 64 + d4];
                    o.x = fmaf(xv.x, wv.x, xv.x);
                    o.y = fmaf(xv.y, wv.y, xv.y);
                    o.z = fmaf(xv.z, wv.z, xv.z);
                    o.w = fmaf(xv.w, wv.w, xv.w);
                }
                bufs[s * 2048 + (r2 + 16) * 64 + d4] = o;
            }
            __syncthreads();                     // tile fully rewritten (single sync)
            if (tid == 0) {
                fence_proxy_async_shared();
                bulk_store(ob + (size_t)(t0 + j) * TILE_BYTES, bufa[s], TILE_BYTES);
                bulk_commit();
                // reissue tile j+4 (only tiles >= NBUF, i.e. at most 2 per CTA);
                // its slot (j-2)%6 was stored 2 iterations ago: wait_group(2)
                // leaves <=2 newest stores pending -> that store has drained.
                int jn = j + 4;
                if (jn >= NBUF && jn < nt) {
                    bulk_wait_group2();
                    mbar_expect_tx(mb[jn % NBUF], TILE_BYTES);
                    bulk_load(bufa[jn % NBUF], xb + (size_t)(t0 + jn) * TILE_BYTES,
                              TILE_BYTES, mb[jn % NBUF]);
                }
            }
        }
        if (tid == 0) bulk_wait_group0();        // drain all stores before exit
        __syncthreads();
    }
}

// ---------------------------------------------------------------------------
extern "C" void kernel_launch(void* const* d_in, const int* in_sizes, int n_in,
                              void* d_out, int out_size) {
    const float* x     = (const float*)d_in[0];
    const int*   len_x = (const int*)d_in[1];
    const float* Ww1_w = (const float*)d_in[2];
    const float* Ww1_b = (const float*)d_in[3];
    const float* Ww2_w = (const float*)d_in[4];
    const float* Ww2_b = (const float*)d_in[5];
    const float* Wb1_w = (const float*)d_in[6];
    const float* Wb1_b = (const float*)d_in[7];
    const float* Wb2_w = (const float*)d_in[8];
    const float* Wb2_b = (const float*)d_in[9];
    float* out = (float*)d_out;

    cudaFuncSetAttribute(fused_kernel,
                         cudaFuncAttributeMaxDynamicSharedMemorySize, DYN_SMEM);
    fused_kernel<<<GRID, NTHREADS, DYN_SMEM>>>(
        x, len_x,
        Ww1_w, Ww1_b, Ww2_w, Ww2_b,
        Wb1_w, Wb1_b, Wb2_w, Wb2_b,
        out);
}

// round 17
// speedup vs baseline: 1.3113x; 1.0743x over previous
#include <cuda_runtime.h>
#include <math.h>
#include <stdint.h>

// Problem constants: B=32, T=1024, D=256, H=256
#define BB 32
#define TT 1024
#define DD 256
#define HH 256
#define GRID 148
#define NTHREADS 1024
#define TILE_ROWS 32
#define TILE_BYTES (TILE_ROWS * DD * 4)      // 32768
#define TILES_PER_BATCH (TT / TILE_ROWS)     // 32
#define NBUF 6                                // load ring (all 6 slots, both phases)
#define DYN_SMEM (NBUF * TILE_BYTES)          // 196608

// Scratch (device globals — no allocation allowed)
__device__ __align__(16) float g_partial[GRID * DD];   // one partial per CTA
__device__ __align__(16) float g_W[BB * DD];
__device__ __align__(16) float g_bias[BB * DD];
// Per-batch dataflow sync. MONOTONIC (never reset) -> CUDA-graph replay safe:
// each launch adds exactly n arrivals to g_cnt[b] and 2 to g_done[b];
// epoch = ticket / n identifies this launch's round.
__device__ unsigned g_cnt[BB];               // phase-1 arrivals per batch
__device__ volatile unsigned g_done[BB];     // MLP completions per batch

// ---------------------------------------------------------------------------
// PTX helpers
// ---------------------------------------------------------------------------
__device__ __forceinline__ unsigned smem_u32(const void* p) {
    return (unsigned)__cvta_generic_to_shared(p);
}
__device__ __forceinline__ void mbar_init(unsigned a, unsigned cnt) {
    asm volatile("mbarrier.init.shared.b64 [%0], %1;" :: "r"(a), "r"(cnt) : "memory");
}
__device__ __forceinline__ void mbar_expect_tx(unsigned a, unsigned bytes) {
    asm volatile("mbarrier.arrive.expect_tx.shared.b64 _, [%0], %1;"
                 :: "r"(a), "r"(bytes) : "memory");
}
__device__ __forceinline__ void mbar_wait(unsigned a, int phase) {
    asm volatile(
        "{\n\t.reg .pred P;\n\t"
        "W_%=:\n\t"
        "mbarrier.try_wait.parity.acquire.cta.shared::cta.b64 P, [%0], %1, 0x989680;\n\t"
        "@P bra D_%=;\n\t"
        "bra W_%=;\n\t"
        "D_%=:\n\t}"
        :: "r"(a), "r"((unsigned)phase) : "memory");
}
__device__ __forceinline__ void bulk_load(unsigned dst_smem, const void* src_gmem,
                                          unsigned bytes, unsigned mbar) {
    asm volatile(
        "cp.async.bulk.shared::cluster.global.mbarrier::complete_tx::bytes "
        "[%0], [%1], %2, [%3];"
        :: "r"(dst_smem), "l"(src_gmem), "r"(bytes), "r"(mbar) : "memory");
}
__device__ __forceinline__ void bulk_store(void* dst_gmem, unsigned src_smem,
                                           unsigned bytes) {
    asm volatile("cp.async.bulk.global.shared::cta.bulk_group [%0], [%1], %2;"
                 :: "l"(dst_gmem), "r"(src_smem), "r"(bytes) : "memory");
}
__device__ __forceinline__ void bulk_commit()      { asm volatile("cp.async.bulk.commit_group;" ::: "memory"); }
__device__ __forceinline__ void bulk_wait_group2() { asm volatile("cp.async.bulk.wait_group 2;" ::: "memory"); }
__device__ __forceinline__ void bulk_wait_group0() { asm volatile("cp.async.bulk.wait_group 0;" ::: "memory"); }
__device__ __forceinline__ void fence_proxy_async_shared() {
    asm volatile("fence.proxy.async.shared::cta;" ::: "memory");
}

__device__ __forceinline__ float gelu_exact(float v) {
    return 0.5f * v * (1.0f + erff(v * 0.70710678118654752f));
}
__device__ __forceinline__ float dot4(float4 a, float4 b) {
    return fmaf(a.x, b.x, fmaf(a.y, b.y, fmaf(a.z, b.z, a.w * b.w)));
}

extern __shared__ __align__(128) char dynsmem[];

// ---------------------------------------------------------------------------
// Persistent kernel, NO global barriers: per-batch dataflow sync.
//   phase1 (R16) -> arrive g_cnt[b] -> [first 2 CTAs of batch: MLP -> g_done]
//   -> all CTAs of batch spin g_done[b] -> phase3 (R16, in-place)
// ---------------------------------------------------------------------------
__global__ __launch_bounds__(NTHREADS, 1) void fused_kernel(
        const float* __restrict__ x,
        const int* __restrict__ len,
        const float* __restrict__ w1w, const float* __restrict__ w1b,
        const float* __restrict__ w2w, const float* __restrict__ w2b,
        const float* __restrict__ q1w, const float* __restrict__ q1b,
        const float* __restrict__ q2w, const float* __restrict__ q2b,
        float* __restrict__ out) {
    __shared__ __align__(16) float c_sh[DD];
    __shared__ __align__(16) float h_sh[HH];
    __shared__ unsigned epoch_sh;
    __shared__ __align__(8) unsigned long long mbar_s[NBUF];

    const int tid = threadIdx.x;
    const int d4  = tid & 63;
    const int r2  = tid >> 6;        // rows r2 and r2+16 of a tile
    const char* xb = (const char*)x;
    char*       ob = (char*)out;

    // Per-batch slab (R10): CTA -> one batch, contiguous tiles (6-8).
    const int b   = (blockIdx.x * BB) / GRID;
    const int lo  = (b * GRID + BB - 1) / BB;
    const int hi  = ((b + 1) * GRID + BB - 1) / BB;
    const int idx = blockIdx.x - lo;
    const int n   = hi - lo;                       // contributors for batch b (4-5)
    const int t0  = b * TILES_PER_BATCH + (idx * TILES_PER_BATCH) / n;
    const int t1  = b * TILES_PER_BATCH + ((idx + 1) * TILES_PER_BATCH) / n;
    const int nt  = t1 - t0;

    unsigned mb[NBUF], bufa[NBUF];
#pragma unroll
    for (int k = 0; k < NBUF; k++) {
        mb[k]   = smem_u32(&mbar_s[k]);
        bufa[k] = smem_u32(dynsmem) + k * TILE_BYTES;
    }
    if (tid == 0) {
#pragma unroll
        for (int k = 0; k < NBUF; k++) mbar_init(mb[k], 1);
    }
    __syncthreads();
    int ph[NBUF] = {0, 0, 0, 0, 0, 0};
    float4* const bufs = (float4*)dynsmem;

    // ---------- Phase 1: reduce via NBUF-deep TMA ring (R16 verbatim) ----------
    {
        if (tid == 0) {
            int pre = nt < NBUF ? nt : NBUF;
            for (int j = 0; j < pre; j++) {
                mbar_expect_tx(mb[j], TILE_BYTES);
                bulk_load(bufa[j], xb + (size_t)(t0 + j) * TILE_BYTES, TILE_BYTES, mb[j]);
            }
        }
        float4 acc0 = make_float4(0.f, 0.f, 0.f, 0.f);
        float4 acc1 = make_float4(0.f, 0.f, 0.f, 0.f);
        for (int i = 0; i < nt; i++) {
            int s = i % NBUF;
            mbar_wait(mb[s], ph[s]); ph[s] ^= 1;
            float4 v0 = bufs[s * 2048 + r2 * 64 + d4];
            float4 v1 = bufs[s * 2048 + (r2 + 16) * 64 + d4];
            acc0.x += v0.x; acc0.y += v0.y; acc0.z += v0.z; acc0.w += v0.w;
            acc1.x += v1.x; acc1.y += v1.y; acc1.z += v1.z; acc1.w += v1.w;
            if (i + NBUF < nt) {                 // reissue (<=2 per launch)
                __syncthreads();
                if (tid == 0) {
                    mbar_expect_tx(mb[s], TILE_BYTES);
                    bulk_load(bufa[s], xb + (size_t)(t0 + i + NBUF) * TILE_BYTES, TILE_BYTES, mb[s]);
                }
            }
        }
        acc0.x += acc1.x; acc0.y += acc1.y; acc0.z += acc1.z; acc0.w += acc1.w;
        bufs[r2 * 64 + d4] = acc0;
        __syncthreads();
        if (tid < 64) {
            float4 a = make_float4(0.f, 0.f, 0.f, 0.f);
#pragma unroll
            for (int r = 0; r < 16; r++) {
                float4 v = bufs[r * 64 + tid];
                a.x += v.x; a.y += v.y; a.z += v.z; a.w += v.w;
            }
            reinterpret_cast<float4*>(g_partial)[blockIdx.x * 64 + tid] = a;
        }
        __syncthreads();
        // arrive on per-batch counter; epoch identifies this launch's round
        if (tid == 0) {
            __threadfence();                             // publish partials
            unsigned tk = atomicAdd(&g_cnt[b], 1u);
            epoch_sh = tk / (unsigned)n;
        }
        // phase-3 prefetch: all NBUF slots (overlaps MLP + spins)
        if (tid == 0) {
            int pre = nt < NBUF ? nt : NBUF;
            for (int j = 0; j < pre; j++) {
                mbar_expect_tx(mb[j], TILE_BYTES);
                bulk_load(bufa[j], xb + (size_t)(t0 + j) * TILE_BYTES, TILE_BYTES, mb[j]);
            }
        }
        __syncthreads();                                 // epoch_sh visible
    }
    const unsigned epoch = epoch_sh;

    // ---------- Phase 2: per-batch MLP on the first 2 CTAs of each batch ----------
    if (idx < 2) {
        // wait for ALL n contributors of batch b (this launch = epoch round)
        if (tid == 0) {
            const unsigned target = (epoch + 1u) * (unsigned)n;
            volatile unsigned* cnt = (volatile unsigned*)&g_cnt[b];
            while (*cnt < target) { __nanosleep(32); }
            __threadfence();                             // order partial reads after
        }
        __syncthreads();

        int branch = idx;
        const float* m1w = branch ? q1w : w1w;
        const float* m1b = branch ? q1b : w1b;
        const float* m2w = branch ? q2w : w2w;
        const float* m2b = branch ? q2b : w2b;
        float* gout = branch ? g_bias : g_W;

        if (tid < DD) {
            float s = 0.0f;
            for (int c = lo; c < hi; c++) s += g_partial[c * DD + tid];
            c_sh[tid] = s / (float)len[b];
        }
        __syncthreads();

        int w = tid >> 5, lane = tid & 31;     // 32 warps x 8 outputs (R10 MLP)
        const float4* c4 = reinterpret_cast<const float4*>(c_sh);
        const float4* h4 = reinterpret_cast<const float4*>(h_sh);
#pragma unroll
        for (int jj = 0; jj < 8; jj++) {
            int o = w * 8 + jj;
            const float4* row = reinterpret_cast<const float4*>(m1w + (size_t)o * DD);
            float acc = dot4(c4[lane], row[lane]) + dot4(c4[lane + 32], row[lane + 32]);
#pragma unroll
            for (int off = 16; off > 0; off >>= 1)
                acc += __shfl_down_sync(0xFFFFFFFFu, acc, off);
            if (lane == 0) h_sh[o] = gelu_exact(acc + m1b[o]);
        }
        __syncthreads();
#pragma unroll
        for (int jj = 0; jj < 8; jj++) {
            int o = w * 8 + jj;
            const float4* row = reinterpret_cast<const float4*>(m2w + (size_t)o * HH);
            float acc = dot4(h4[lane], row[lane]) + dot4(h4[lane + 32], row[lane + 32]);
#pragma unroll
            for (int off = 16; off > 0; off >>= 1)
                acc += __shfl_down_sync(0xFFFFFFFFu, acc, off);
            if (lane == 0) gout[b * DD + o] = acc + m2b[o];
        }
        __syncthreads();
        if (tid == 0) {
            __threadfence();                             // publish gout
            atomicAdd((unsigned*)&g_done[b], 1u);
        }
    }

    // ---------- wait for this batch's MLP (both branches) ----------
    if (tid == 0) {
        const unsigned dtarget = 2u * (epoch + 1u);
        while (g_done[b] < dtarget) { __nanosleep(32); }
        __threadfence();                                 // order g_W/g_bias reads after
    }
    __syncthreads();

    // ---------- Phase 3: in-place apply (R16 verbatim) ----------
    {
        const int L = __ldg(&len[b]);
        float4 wv = reinterpret_cast<const float4*>(g_W)[b * 64 + d4];
        float4 bv = reinterpret_cast<const float4*>(g_bias)[b * 64 + d4];
        const float4 zero = make_float4(0.f, 0.f, 0.f, 0.f);

        for (int j = 0; j < nt; j++) {
            int s = j % NBUF;
            mbar_wait(mb[s], ph[s]); ph[s] ^= 1;

            int tbase = (t0 + j) * TILE_ROWS - b * TT;
            {
                int t = tbase + r2;
                float4 o = zero;
                if (t < L) {
                    float4 xv = bufs[s * 2048 + r2 * 64 + d4];
                    o.x = fmaf(xv.x, wv.x, xv.x);
                    o.y = fmaf(xv.y, wv.y, xv.y);
                    o.z = fmaf(xv.z, wv.z, xv.z);
                    o.w = fmaf(xv.w, wv.w, xv.w);
                    if (t == 0) { o.x += bv.x; o.y += bv.y; o.z += bv.z; o.w += bv.w; }
                }
                bufs[s * 2048 + r2 * 64 + d4] = o;
            }
            {
                int t = tbase + r2 + 16;
                float4 o = zero;
                if (t < L) {
                    float4 xv = bufs[s * 2048 + (r2 + 16) * 64 + d4];
                    o.x = fmaf(xv.x, wv.x, xv.x);
                    o.y = fmaf(xv.y, wv.y, xv.y);
                    o.z = fmaf(xv.z, wv.z, xv.z);
                    o.w = fmaf(xv.w, wv.w, xv.w);
                }
                bufs[s * 2048 + (r2 + 16) * 64 + d4] = o;
            }
            __syncthreads();                     // tile fully rewritten
            if (tid == 0) {
                fence_proxy_async_shared();
                bulk_store(ob + (size_t)(t0 + j) * TILE_BYTES, bufa[s], TILE_BYTES);
                bulk_commit();
                int jn = j + 4;
                if (jn >= NBUF && jn < nt) {     // <=2 reissues; slot store drained
                    bulk_wait_group2();
                    mbar_expect_tx(mb[jn % NBUF], TILE_BYTES);
                    bulk_load(bufa[jn % NBUF], xb + (size_t)(t0 + jn) * TILE_BYTES,
                              TILE_BYTES, mb[jn % NBUF]);
                }
            }
        }
        if (tid == 0) bulk_wait_group0();        // drain all stores before exit
        __syncthreads();
    }
}

// ---------------------------------------------------------------------------
extern "C" void kernel_launch(void* const* d_in, const int* in_sizes, int n_in,
                              void* d_out, int out_size) {
    const float* x     = (const float*)d_in[0];
    const int*   len_x = (const int*)d_in[1];
    const float* Ww1_w = (const float*)d_in[2];
    const float* Ww1_b = (const float*)d_in[3];
    const float* Ww2_w = (const float*)d_in[4];
    const float* Ww2_b = (const float*)d_in[5];
    const float* Wb1_w = (const float*)d_in[6];
    const float* Wb1_b = (const float*)d_in[7];
    const float* Wb2_w = (const float*)d_in[8];
    const float* Wb2_b = (const float*)d_in[9];
    float* out = (float*)d_out;

    cudaFuncSetAttribute(fused_kernel,
                         cudaFuncAttributeMaxDynamicSharedMemorySize, DYN_SMEM);
    fused_kernel<<<GRID, NTHREADS, DYN_SMEM>>>(
        x, len_x,
        Ww1_w, Ww1_b, Ww2_w, Ww2_b,
        Wb1_w, Wb1_b, Wb2_w, Wb2_b,
        out);
}